// round 5
// baseline (speedup 1.0000x reference)
#include <cuda_runtime.h>

#define Tt 2048
#define Dd 1024
#define Ff 4096
#define Ee 8
#define NROWS (Tt * 2)   // T * TOPK

typedef unsigned long long u64;

// Scratch (device globals: allocation-free, graph-safe)
__device__ float g_fuse[(size_t)NROWS * Ff];   // 64 MB, compacted by expert bucket
__device__ float g_down[(size_t)NROWS * Dd];   // 16 MB, indexed by rid = t*2+k
__device__ int   g_bucket[NROWS];              // rid list grouped by expert
__device__ int   g_offs[Ee + 1];
__device__ float g_topw[NROWS];
__device__ int   g_topidx[NROWS];

// ---------- packed fp32x2 helpers (FFMA2 path: 2x FFMA throughput) ----------
__device__ __forceinline__ u64 pack2(float v) {
    unsigned u = __float_as_uint(v);
    u64 r;
    asm("mov.b64 %0, {%1, %2};" : "=l"(r) : "r"(u), "r"(u));
    return r;
}
__device__ __forceinline__ void unpack2(u64 v, float& lo, float& hi) {
    unsigned a, b;
    asm("mov.b64 {%0, %1}, %2;" : "=r"(a), "=r"(b) : "l"(v));
    lo = __uint_as_float(a);
    hi = __uint_as_float(b);
}
__device__ __forceinline__ void fma2(u64& d, u64 a, u64 b) {
    asm("fma.rn.f32x2 %0, %1, %2, %0;" : "+l"(d) : "l"(a), "l"(b));
}
__device__ __forceinline__ float silu(float g) {
    return g / (1.f + __expf(-g));
}

// ---------------------- 1. Router: logits + top2 + softmax ----------------------
__global__ void router_kernel(const float* __restrict__ x, const float* __restrict__ rw) {
    int gw   = (blockIdx.x * blockDim.x + threadIdx.x) >> 5;
    int lane = threadIdx.x & 31;
    if (gw >= Tt) return;
    const float* xr = x + (size_t)gw * Dd;
    float acc[Ee];
#pragma unroll
    for (int e = 0; e < Ee; e++) acc[e] = 0.f;
    for (int d = lane; d < Dd; d += 32) {
        float xv = xr[d];
        const float4* r = (const float4*)(rw + (size_t)d * Ee);
        float4 r0 = r[0], r1 = r[1];
        acc[0] += xv * r0.x; acc[1] += xv * r0.y;
        acc[2] += xv * r0.z; acc[3] += xv * r0.w;
        acc[4] += xv * r1.x; acc[5] += xv * r1.y;
        acc[6] += xv * r1.z; acc[7] += xv * r1.w;
    }
#pragma unroll
    for (int e = 0; e < Ee; e++) {
#pragma unroll
        for (int off = 16; off > 0; off >>= 1)
            acc[e] += __shfl_xor_sync(0xffffffffu, acc[e], off);
    }
    if (lane == 0) {
        int i0 = 0;
#pragma unroll
        for (int e = 1; e < Ee; e++) if (acc[e] > acc[i0]) i0 = e;
        int i1 = (i0 == 0) ? 1 : 0;
#pragma unroll
        for (int e = 0; e < Ee; e++) if (e != i0 && acc[e] > acc[i1]) i1 = e;
        float ex = __expf(acc[i1] - acc[i0]);   // second <= first
        float w0 = 1.f / (1.f + ex);
        float w1 = ex * w0;
        g_topidx[gw * 2 + 0] = i0;
        g_topidx[gw * 2 + 1] = i1;
        g_topw[gw * 2 + 0] = w0;
        g_topw[gw * 2 + 1] = w1;
    }
}

// ---------------------- 2. Bucket compaction (single block) ----------------------
__global__ void compact_kernel() {
    __shared__ int s_cnt[Ee], s_cur[Ee], s_off[Ee + 1];
    int tid = threadIdx.x;
    if (tid < Ee) { s_cnt[tid] = 0; s_cur[tid] = 0; }
    __syncthreads();
    for (int r = tid; r < NROWS; r += blockDim.x)
        atomicAdd(&s_cnt[g_topidx[r]], 1);
    __syncthreads();
    if (tid == 0) {
        int acc = 0;
        for (int e = 0; e < Ee; e++) { s_off[e] = acc; acc += s_cnt[e]; }
        s_off[Ee] = acc;
        for (int e = 0; e <= Ee; e++) g_offs[e] = s_off[e];
    }
    __syncthreads();
    for (int r = tid; r < NROWS; r += blockDim.x) {
        int e = g_topidx[r];
        int p = atomicAdd(&s_cur[e], 1);
        g_bucket[s_off[e] + p] = r;
    }
}

// ---------------------- 3. GEMM1: gathered X @ (Wg, Wu), fused SiLU ----------------------
// Block: 128(M) x 64(N) x 16(K), 256 threads, thread tile 8x4 per matrix (f32x2-packed rows)
__global__ void __launch_bounds__(256) gemm1_kernel(
    const float* __restrict__ x,
    const float* __restrict__ wg,
    const float* __restrict__ wu)
{
    const int e   = blockIdx.z;
    const int off = g_offs[e];
    const int n_e = g_offs[e + 1] - off;
    const int m0  = blockIdx.y * 128;
    if (m0 >= n_e) return;
    const int n0  = blockIdx.x * 64;

    __shared__ float As[2][16][128];
    __shared__ float Bg[2][16][64];
    __shared__ float Bu[2][16][64];

    const int tid   = threadIdx.x;
    const int arow0 = tid >> 2;          // 0..63
    const int arow1 = arow0 + 64;
    const int ak    = (tid & 3) << 2;    // 0,4,8,12
    const int brow  = tid >> 4;          // 0..15
    const int bcol  = (tid & 15) << 2;   // 0..60

    // Gathered A rows (clamped: out-of-range rows duplicate the last valid row,
    // their results are discarded in the epilogue)
    const int tok0 = g_bucket[off + min(m0 + arow0, n_e - 1)] >> 1;
    const int tok1 = g_bucket[off + min(m0 + arow1, n_e - 1)] >> 1;
    const float* xa0 = x + (size_t)tok0 * Dd + ak;
    const float* xa1 = x + (size_t)tok1 * Dd + ak;
    const float* wge = wg + (size_t)e * Dd * Ff + (size_t)brow * Ff + n0 + bcol;
    const float* wue = wu + (size_t)e * Dd * Ff + (size_t)brow * Ff + n0 + bcol;

    float4 ra0 = *(const float4*)xa0;
    float4 ra1 = *(const float4*)xa1;
    float4 rbg = *(const float4*)wge;
    float4 rbu = *(const float4*)wue;

    u64 cg[4][4], cu[4][4];
#pragma unroll
    for (int i = 0; i < 4; i++)
#pragma unroll
        for (int j = 0; j < 4; j++) { cg[i][j] = 0ull; cu[i][j] = 0ull; }

    const int ty = tid >> 4, tx = tid & 15;
    const int rbase = ty * 8, cbase = tx * 4;

    const int NIT = Dd / 16;   // 64
    for (int it = 0; it < NIT; ++it) {
        const int s = it & 1;
        As[s][ak + 0][arow0] = ra0.x; As[s][ak + 1][arow0] = ra0.y;
        As[s][ak + 2][arow0] = ra0.z; As[s][ak + 3][arow0] = ra0.w;
        As[s][ak + 0][arow1] = ra1.x; As[s][ak + 1][arow1] = ra1.y;
        As[s][ak + 2][arow1] = ra1.z; As[s][ak + 3][arow1] = ra1.w;
        *(float4*)&Bg[s][brow][bcol] = rbg;
        *(float4*)&Bu[s][brow][bcol] = rbu;
        __syncthreads();

        if (it + 1 < NIT) {
            const int k0 = (it + 1) * 16;
            ra0 = *(const float4*)(xa0 + k0);
            ra1 = *(const float4*)(xa1 + k0);
            rbg = *(const float4*)(wge + (size_t)k0 * Ff);
            rbu = *(const float4*)(wue + (size_t)k0 * Ff);
        }

#pragma unroll
        for (int kk = 0; kk < 16; ++kk) {
            const u64* ap = (const u64*)&As[s][kk][rbase];
            u64 a[4];
            a[0] = ap[0]; a[1] = ap[1]; a[2] = ap[2]; a[3] = ap[3];
            float4 bg4 = *(const float4*)&Bg[s][kk][cbase];
            float4 bu4 = *(const float4*)&Bu[s][kk][cbase];
            float gs[4] = {bg4.x, bg4.y, bg4.z, bg4.w};
            float us[4] = {bu4.x, bu4.y, bu4.z, bu4.w};
#pragma unroll
            for (int j = 0; j < 4; j++) {
                u64 b = pack2(gs[j]);
#pragma unroll
                for (int i = 0; i < 4; i++) fma2(cg[i][j], a[i], b);
            }
#pragma unroll
            for (int j = 0; j < 4; j++) {
                u64 b = pack2(us[j]);
#pragma unroll
                for (int i = 0; i < 4; i++) fma2(cu[i][j], a[i], b);
            }
        }
    }

    // Epilogue: fuse = silu(gate) * up  -> compacted g_fuse rows
#pragma unroll
    for (int i2 = 0; i2 < 4; i2++) {
        float glo[4], ghi[4], ulo[4], uhi[4];
#pragma unroll
        for (int j = 0; j < 4; j++) {
            unpack2(cg[i2][j], glo[j], ghi[j]);
            unpack2(cu[i2][j], ulo[j], uhi[j]);
        }
        int r = m0 + rbase + 2 * i2;
        if (r < n_e) {
            float4 v;
            v.x = silu(glo[0]) * ulo[0];
            v.y = silu(glo[1]) * ulo[1];
            v.z = silu(glo[2]) * ulo[2];
            v.w = silu(glo[3]) * ulo[3];
            *(float4*)&g_fuse[(size_t)(off + r) * Ff + n0 + cbase] = v;
        }
        if (r + 1 < n_e) {
            float4 v;
            v.x = silu(ghi[0]) * uhi[0];
            v.y = silu(ghi[1]) * uhi[1];
            v.z = silu(ghi[2]) * uhi[2];
            v.w = silu(ghi[3]) * uhi[3];
            *(float4*)&g_fuse[(size_t)(off + r + 1) * Ff + n0 + cbase] = v;
        }
    }
}

// ---------------------- 4. GEMM2: fuse @ Wd -> g_down[rid] ----------------------
// Block: 128(M) x 128(N) x 16(K), 256 threads, thread tile 8x8
__global__ void __launch_bounds__(256) gemm2_kernel(const float* __restrict__ wd)
{
    const int e   = blockIdx.z;
    const int off = g_offs[e];
    const int n_e = g_offs[e + 1] - off;
    const int m0  = blockIdx.y * 128;
    if (m0 >= n_e) return;
    const int n0  = blockIdx.x * 128;

    __shared__ float As[2][16][128];
    __shared__ float Bs[2][16][128];

    const int tid   = threadIdx.x;
    const int arow0 = tid >> 2;
    const int arow1 = arow0 + 64;
    const int ak    = (tid & 3) << 2;
    const int brow0 = tid >> 5;            // 0..7
    const int brow1 = brow0 + 8;
    const int bcol  = (tid & 31) << 2;     // 0..124

    const int ar0 = off + min(m0 + arow0, n_e - 1);
    const int ar1 = off + min(m0 + arow1, n_e - 1);
    const float* fa0 = g_fuse + (size_t)ar0 * Ff + ak;
    const float* fa1 = g_fuse + (size_t)ar1 * Ff + ak;
    const float* wde = wd + (size_t)e * Ff * Dd + n0 + bcol;

    float4 ra0 = *(const float4*)fa0;
    float4 ra1 = *(const float4*)fa1;
    float4 rb0 = *(const float4*)(wde + (size_t)brow0 * Dd);
    float4 rb1 = *(const float4*)(wde + (size_t)brow1 * Dd);

    u64 c[4][8];
#pragma unroll
    for (int i = 0; i < 4; i++)
#pragma unroll
        for (int j = 0; j < 8; j++) c[i][j] = 0ull;

    const int ty = tid >> 4, tx = tid & 15;
    const int rbase = ty * 8, cbase = tx * 8;

    const int NIT = Ff / 16;   // 256
    for (int it = 0; it < NIT; ++it) {
        const int s = it & 1;
        As[s][ak + 0][arow0] = ra0.x; As[s][ak + 1][arow0] = ra0.y;
        As[s][ak + 2][arow0] = ra0.z; As[s][ak + 3][arow0] = ra0.w;
        As[s][ak + 0][arow1] = ra1.x; As[s][ak + 1][arow1] = ra1.y;
        As[s][ak + 2][arow1] = ra1.z; As[s][ak + 3][arow1] = ra1.w;
        *(float4*)&Bs[s][brow0][bcol] = rb0;
        *(float4*)&Bs[s][brow1][bcol] = rb1;
        __syncthreads();

        if (it + 1 < NIT) {
            const int k0 = (it + 1) * 16;
            ra0 = *(const float4*)(fa0 + k0);
            ra1 = *(const float4*)(fa1 + k0);
            rb0 = *(const float4*)(wde + (size_t)(k0 + brow0) * Dd);
            rb1 = *(const float4*)(wde + (size_t)(k0 + brow1) * Dd);
        }

#pragma unroll
        for (int kk = 0; kk < 16; ++kk) {
            const u64* ap = (const u64*)&As[s][kk][rbase];
            u64 a[4];
            a[0] = ap[0]; a[1] = ap[1]; a[2] = ap[2]; a[3] = ap[3];
            float4 b4a = *(const float4*)&Bs[s][kk][cbase];
            float4 b4b = *(const float4*)&Bs[s][kk][cbase + 4];
            float bs[8] = {b4a.x, b4a.y, b4a.z, b4a.w, b4b.x, b4b.y, b4b.z, b4b.w};
#pragma unroll
            for (int j = 0; j < 8; j++) {
                u64 b = pack2(bs[j]);
#pragma unroll
                for (int i = 0; i < 4; i++) fma2(c[i][j], a[i], b);
            }
        }
    }

    // Epilogue: scatter rows by rid (deterministic: each rid written once)
#pragma unroll
    for (int i2 = 0; i2 < 4; i2++) {
        int r = m0 + rbase + 2 * i2;
        float lo[8], hi[8];
#pragma unroll
        for (int j = 0; j < 8; j++) unpack2(c[i2][j], lo[j], hi[j]);
        if (r < n_e) {
            int rid = g_bucket[off + r];
            float* dst = g_down + (size_t)rid * Dd + n0 + cbase;
            *(float4*)dst       = make_float4(lo[0], lo[1], lo[2], lo[3]);
            *(float4*)(dst + 4) = make_float4(lo[4], lo[5], lo[6], lo[7]);
        }
        if (r + 1 < n_e) {
            int rid = g_bucket[off + r + 1];
            float* dst = g_down + (size_t)rid * Dd + n0 + cbase;
            *(float4*)dst       = make_float4(hi[0], hi[1], hi[2], hi[3]);
            *(float4*)(dst + 4) = make_float4(hi[4], hi[5], hi[6], hi[7]);
        }
    }
}

// ---------------------- 5. Weighted combine ----------------------
__global__ void combine_kernel(float* __restrict__ out) {
    int i = blockIdx.x * blockDim.x + threadIdx.x;
    const int n4 = Tt * Dd / 4;
    if (i >= n4) return;
    int t = i / (Dd / 4);
    int c = i % (Dd / 4);
    float w0 = g_topw[t * 2 + 0];
    float w1 = g_topw[t * 2 + 1];
    float4 a = ((const float4*)(g_down + (size_t)(t * 2 + 0) * Dd))[c];
    float4 b = ((const float4*)(g_down + (size_t)(t * 2 + 1) * Dd))[c];
    float4 r;
    r.x = w0 * a.x + w1 * b.x;
    r.y = w0 * a.y + w1 * b.y;
    r.z = w0 * a.z + w1 * b.z;
    r.w = w0 * a.w + w1 * b.w;
    ((float4*)out)[i] = r;
}

// ---------------------- launch ----------------------
extern "C" void kernel_launch(void* const* d_in, const int* in_sizes, int n_in,
                              void* d_out, int out_size) {
    const float* x  = (const float*)d_in[0];
    const float* rw = (const float*)d_in[1];
    const float* wg = (const float*)d_in[2];
    const float* wu = (const float*)d_in[3];
    const float* wd = (const float*)d_in[4];
    float* out = (float*)d_out;

    router_kernel<<<Tt / 8, 256>>>(x, rw);
    compact_kernel<<<1, 256>>>();

    dim3 g1(Ff / 64, (Tt + 127) / 128, Ee);
    gemm1_kernel<<<g1, 256>>>(x, wg, wu);

    dim3 g2(Dd / 128, (Tt + 127) / 128, Ee);
    gemm2_kernel<<<g2, 256>>>(wd);

    combine_kernel<<<(Tt * Dd / 4 + 255) / 256, 256>>>(out);
}

// round 7
// speedup vs baseline: 1.8006x; 1.8006x over previous
#include <cuda_runtime.h>

#define Tt 2048
#define Dd 1024
#define Ff 4096
#define Ee 8
#define NROWS (Tt * 2)

typedef unsigned int u32;

// ---------------- scratch (device globals: allocation-free, graph-safe) ----------------
__device__ float g_fuse[(size_t)NROWS * Ff];   // compacted by expert bucket
__device__ float g_down[(size_t)NROWS * Dd];   // indexed by rid = t*2+k
__device__ int   g_bucket[NROWS];
__device__ int   g_offs[Ee + 1];
__device__ float g_topw[NROWS];
__device__ int   g_topidx[NROWS];

// ---------------- helpers ----------------
__device__ __forceinline__ u32 f2tf(float f) {
    u32 u;
    asm("cvt.rna.tf32.f32 %0, %1;" : "=r"(u) : "f"(f));
    return u;
}
__device__ __forceinline__ void mma8(float* c, const u32* a, u32 b0, u32 b1) {
    asm volatile(
        "mma.sync.aligned.m16n8k8.row.col.f32.tf32.tf32.f32 "
        "{%0,%1,%2,%3}, {%4,%5,%6,%7}, {%8,%9}, {%0,%1,%2,%3};"
        : "+f"(c[0]), "+f"(c[1]), "+f"(c[2]), "+f"(c[3])
        : "r"(a[0]), "r"(a[1]), "r"(a[2]), "r"(a[3]), "r"(b0), "r"(b1));
}
__device__ __forceinline__ float silu(float g) { return g / (1.f + __expf(-g)); }

// smem tile geometry: [16 k][136 stride] u32 (tf32 bits); bank = (8*tig + g + const) % 32 -> conflict-free
#define TSTRIDE 136
#define TILE_U32 (16 * TSTRIDE)   // 2176

// ---------------------- 1. Router ----------------------
__global__ void router_kernel(const float* __restrict__ x, const float* __restrict__ rw) {
    int gw   = (blockIdx.x * blockDim.x + threadIdx.x) >> 5;
    int lane = threadIdx.x & 31;
    if (gw >= Tt) return;
    const float* xr = x + (size_t)gw * Dd;
    float acc[Ee];
#pragma unroll
    for (int e = 0; e < Ee; e++) acc[e] = 0.f;
    for (int d = lane; d < Dd; d += 32) {
        float xv = xr[d];
        const float4* r = (const float4*)(rw + (size_t)d * Ee);
        float4 r0 = r[0], r1 = r[1];
        acc[0] += xv * r0.x; acc[1] += xv * r0.y;
        acc[2] += xv * r0.z; acc[3] += xv * r0.w;
        acc[4] += xv * r1.x; acc[5] += xv * r1.y;
        acc[6] += xv * r1.z; acc[7] += xv * r1.w;
    }
#pragma unroll
    for (int e = 0; e < Ee; e++) {
#pragma unroll
        for (int off = 16; off > 0; off >>= 1)
            acc[e] += __shfl_xor_sync(0xffffffffu, acc[e], off);
    }
    if (lane == 0) {
        int i0 = 0;
#pragma unroll
        for (int e = 1; e < Ee; e++) if (acc[e] > acc[i0]) i0 = e;
        int i1 = (i0 == 0) ? 1 : 0;
#pragma unroll
        for (int e = 0; e < Ee; e++) if (e != i0 && acc[e] > acc[i1]) i1 = e;
        float ex = __expf(acc[i1] - acc[i0]);
        float w0 = 1.f / (1.f + ex);
        g_topidx[gw * 2 + 0] = i0;
        g_topidx[gw * 2 + 1] = i1;
        g_topw[gw * 2 + 0] = w0;
        g_topw[gw * 2 + 1] = ex * w0;
    }
}

// ---------------------- 2. Bucket compaction ----------------------
__global__ void compact_kernel() {
    __shared__ int s_cnt[Ee], s_cur[Ee], s_off[Ee + 1];
    int tid = threadIdx.x;
    if (tid < Ee) { s_cnt[tid] = 0; s_cur[tid] = 0; }
    __syncthreads();
    for (int r = tid; r < NROWS; r += blockDim.x)
        atomicAdd(&s_cnt[g_topidx[r]], 1);
    __syncthreads();
    if (tid == 0) {
        int acc = 0;
        for (int e = 0; e < Ee; e++) { s_off[e] = acc; acc += s_cnt[e]; }
        s_off[Ee] = acc;
        for (int e = 0; e <= Ee; e++) g_offs[e] = s_off[e];
    }
    __syncthreads();
    for (int r = tid; r < NROWS; r += blockDim.x) {
        int e = g_topidx[r];
        int p = atomicAdd(&s_cur[e], 1);
        g_bucket[s_off[e] + p] = r;
    }
}

// ---------------------- 3. GEMM1: tf32 mma.sync, gate+up fused + SiLU ----------------------
// block 128M x (128N gate + 128N up), K-stage 16, 256 thr, warps 2Mx4N, warp tile 64x32
#define G1_SMEM_BYTES (2 * 3 * TILE_U32 * 4)   // 52224

__global__ void __launch_bounds__(256, 1) gemm1_mma(
    const float* __restrict__ x,
    const float* __restrict__ wg,
    const float* __restrict__ wu)
{
    extern __shared__ u32 sm[];
    const int e   = blockIdx.z;
    const int off = g_offs[e];
    const int n_e = g_offs[e + 1] - off;
    const int m0  = blockIdx.y * 128;
    if (m0 >= n_e) return;
    const int n0  = blockIdx.x * 128;

    const int tid = threadIdx.x, wid = tid >> 5, lane = tid & 31;
    const int g = lane >> 2, tig = lane & 3;
    const int wm = wid >> 2, wn = wid & 3;

    // loaders: A: m=tid&127, k-half=tid>>7 ; B: k=tid>>5 (+8), n4=(tid&31)*4
    const int mrow = tid & 127, kh = tid >> 7;
    const int kb = tid >> 5, nb4 = (tid & 31) << 2;
    const int rid = g_bucket[off + min(m0 + mrow, n_e - 1)];
    const float* aptr = x + (size_t)(rid >> 1) * Dd + kh * 8;
    const float* gptr = wg + (size_t)e * Dd * Ff + (size_t)kb * Ff + n0 + nb4;
    const float* uptr = wu + (size_t)e * Dd * Ff + (size_t)kb * Ff + n0 + nb4;

    float4 pa0 = *(const float4*)aptr, pa1 = *(const float4*)(aptr + 4);
    float4 pg0 = *(const float4*)gptr, pg1 = *(const float4*)(gptr + (size_t)8 * Ff);
    float4 pu0 = *(const float4*)uptr, pu1 = *(const float4*)(uptr + (size_t)8 * Ff);

    float cg[4][4][4], cu[4][4][4];
#pragma unroll
    for (int i = 0; i < 4; i++)
#pragma unroll
        for (int j = 0; j < 4; j++)
#pragma unroll
            for (int r = 0; r < 4; r++) { cg[i][j][r] = 0.f; cu[i][j][r] = 0.f; }

    const int NIT = Dd / 16;   // 64
#pragma unroll 1
    for (int it = 0; it < NIT; ++it) {
        const int s = it & 1;
        u32* As = sm + s * TILE_U32;
        u32* Bg = sm + 2 * TILE_U32 + s * TILE_U32;
        u32* Bu = sm + 4 * TILE_U32 + s * TILE_U32;

        // STS (cvt to tf32 at store)
        As[(kh * 8 + 0) * TSTRIDE + mrow] = f2tf(pa0.x);
        As[(kh * 8 + 1) * TSTRIDE + mrow] = f2tf(pa0.y);
        As[(kh * 8 + 2) * TSTRIDE + mrow] = f2tf(pa0.z);
        As[(kh * 8 + 3) * TSTRIDE + mrow] = f2tf(pa0.w);
        As[(kh * 8 + 4) * TSTRIDE + mrow] = f2tf(pa1.x);
        As[(kh * 8 + 5) * TSTRIDE + mrow] = f2tf(pa1.y);
        As[(kh * 8 + 6) * TSTRIDE + mrow] = f2tf(pa1.z);
        As[(kh * 8 + 7) * TSTRIDE + mrow] = f2tf(pa1.w);
        *(uint4*)&Bg[kb * TSTRIDE + nb4]       = make_uint4(f2tf(pg0.x), f2tf(pg0.y), f2tf(pg0.z), f2tf(pg0.w));
        *(uint4*)&Bg[(kb + 8) * TSTRIDE + nb4] = make_uint4(f2tf(pg1.x), f2tf(pg1.y), f2tf(pg1.z), f2tf(pg1.w));
        *(uint4*)&Bu[kb * TSTRIDE + nb4]       = make_uint4(f2tf(pu0.x), f2tf(pu0.y), f2tf(pu0.z), f2tf(pu0.w));
        *(uint4*)&Bu[(kb + 8) * TSTRIDE + nb4] = make_uint4(f2tf(pu1.x), f2tf(pu1.y), f2tf(pu1.z), f2tf(pu1.w));
        __syncthreads();

        if (it + 1 < NIT) {
            aptr += 16;
            gptr += (size_t)16 * Ff;
            uptr += (size_t)16 * Ff;
            pa0 = *(const float4*)aptr; pa1 = *(const float4*)(aptr + 4);
            pg0 = *(const float4*)gptr; pg1 = *(const float4*)(gptr + (size_t)8 * Ff);
            pu0 = *(const float4*)uptr; pu1 = *(const float4*)(uptr + (size_t)8 * Ff);
        }

#pragma unroll
        for (int ks = 0; ks < 2; ++ks) {
            const int kk = ks * 8;
            u32 a[4][4];
#pragma unroll
            for (int mt = 0; mt < 4; mt++) {
                const int mb = wm * 64 + mt * 16 + g;
                a[mt][0] = As[(kk + tig) * TSTRIDE + mb];
                a[mt][1] = As[(kk + tig) * TSTRIDE + mb + 8];
                a[mt][2] = As[(kk + tig + 4) * TSTRIDE + mb];
                a[mt][3] = As[(kk + tig + 4) * TSTRIDE + mb + 8];
            }
#pragma unroll
            for (int nt = 0; nt < 4; nt++) {
                const int nb = wn * 32 + nt * 8 + g;
                u32 bg0 = Bg[(kk + tig) * TSTRIDE + nb];
                u32 bg1 = Bg[(kk + tig + 4) * TSTRIDE + nb];
                u32 bu0 = Bu[(kk + tig) * TSTRIDE + nb];
                u32 bu1 = Bu[(kk + tig + 4) * TSTRIDE + nb];
#pragma unroll
                for (int mt = 0; mt < 4; mt++) {
                    mma8(cg[mt][nt], a[mt], bg0, bg1);
                    mma8(cu[mt][nt], a[mt], bu0, bu1);
                }
            }
        }
        __syncthreads();
    }

    // epilogue: fuse = silu(gate) * up
#pragma unroll
    for (int mt = 0; mt < 4; mt++) {
#pragma unroll
        for (int nt = 0; nt < 4; nt++) {
            const int r0 = wm * 64 + mt * 16 + g;
            const int n  = n0 + wn * 32 + nt * 8 + 2 * tig;
            if (m0 + r0 < n_e) {
                float2 v;
                v.x = silu(cg[mt][nt][0]) * cu[mt][nt][0];
                v.y = silu(cg[mt][nt][1]) * cu[mt][nt][1];
                *(float2*)&g_fuse[(size_t)(off + m0 + r0) * Ff + n] = v;
            }
            if (m0 + r0 + 8 < n_e) {
                float2 v;
                v.x = silu(cg[mt][nt][2]) * cu[mt][nt][2];
                v.y = silu(cg[mt][nt][3]) * cu[mt][nt][3];
                *(float2*)&g_fuse[(size_t)(off + m0 + r0 + 8) * Ff + n] = v;
            }
        }
    }
}

// ---------------------- 4. GEMM2: tf32 mma.sync down-proj ----------------------
#define G2_SMEM_BYTES (2 * 2 * TILE_U32 * 4)   // 34816

__global__ void __launch_bounds__(256, 1) gemm2_mma(const float* __restrict__ wd)
{
    extern __shared__ u32 sm[];
    const int e   = blockIdx.z;
    const int off = g_offs[e];
    const int n_e = g_offs[e + 1] - off;
    const int m0  = blockIdx.y * 128;
    if (m0 >= n_e) return;
    const int n0  = blockIdx.x * 128;

    const int tid = threadIdx.x, wid = tid >> 5, lane = tid & 31;
    const int g = lane >> 2, tig = lane & 3;
    const int wm = wid >> 2, wn = wid & 3;

    const int mrow = tid & 127, kh = tid >> 7;
    const int kb = tid >> 5, nb4 = (tid & 31) << 2;
    const int arow = off + min(m0 + mrow, n_e - 1);
    const float* aptr = g_fuse + (size_t)arow * Ff + kh * 8;
    const float* bptr = wd + (size_t)e * Ff * Dd + (size_t)kb * Dd + n0 + nb4;

    float4 pa0 = *(const float4*)aptr, pa1 = *(const float4*)(aptr + 4);
    float4 pb0 = *(const float4*)bptr, pb1 = *(const float4*)(bptr + (size_t)8 * Dd);

    float c[4][4][4];
#pragma unroll
    for (int i = 0; i < 4; i++)
#pragma unroll
        for (int j = 0; j < 4; j++)
#pragma unroll
            for (int r = 0; r < 4; r++) c[i][j][r] = 0.f;

    const int NIT = Ff / 16;   // 256
#pragma unroll 1
    for (int it = 0; it < NIT; ++it) {
        const int s = it & 1;
        u32* As = sm + s * TILE_U32;
        u32* Bs = sm + 2 * TILE_U32 + s * TILE_U32;

        As[(kh * 8 + 0) * TSTRIDE + mrow] = f2tf(pa0.x);
        As[(kh * 8 + 1) * TSTRIDE + mrow] = f2tf(pa0.y);
        As[(kh * 8 + 2) * TSTRIDE + mrow] = f2tf(pa0.z);
        As[(kh * 8 + 3) * TSTRIDE + mrow] = f2tf(pa0.w);
        As[(kh * 8 + 4) * TSTRIDE + mrow] = f2tf(pa1.x);
        As[(kh * 8 + 5) * TSTRIDE + mrow] = f2tf(pa1.y);
        As[(kh * 8 + 6) * TSTRIDE + mrow] = f2tf(pa1.z);
        As[(kh * 8 + 7) * TSTRIDE + mrow] = f2tf(pa1.w);
        *(uint4*)&Bs[kb * TSTRIDE + nb4]       = make_uint4(f2tf(pb0.x), f2tf(pb0.y), f2tf(pb0.z), f2tf(pb0.w));
        *(uint4*)&Bs[(kb + 8) * TSTRIDE + nb4] = make_uint4(f2tf(pb1.x), f2tf(pb1.y), f2tf(pb1.z), f2tf(pb1.w));
        __syncthreads();

        if (it + 1 < NIT) {
            aptr += 16;
            bptr += (size_t)16 * Dd;
            pa0 = *(const float4*)aptr; pa1 = *(const float4*)(aptr + 4);
            pb0 = *(const float4*)bptr; pb1 = *(const float4*)(bptr + (size_t)8 * Dd);
        }

#pragma unroll
        for (int ks = 0; ks < 2; ++ks) {
            const int kk = ks * 8;
            u32 a[4][4];
#pragma unroll
            for (int mt = 0; mt < 4; mt++) {
                const int mb = wm * 64 + mt * 16 + g;
                a[mt][0] = As[(kk + tig) * TSTRIDE + mb];
                a[mt][1] = As[(kk + tig) * TSTRIDE + mb + 8];
                a[mt][2] = As[(kk + tig + 4) * TSTRIDE + mb];
                a[mt][3] = As[(kk + tig + 4) * TSTRIDE + mb + 8];
            }
#pragma unroll
            for (int nt = 0; nt < 4; nt++) {
                const int nb = wn * 32 + nt * 8 + g;
                u32 b0 = Bs[(kk + tig) * TSTRIDE + nb];
                u32 b1 = Bs[(kk + tig + 4) * TSTRIDE + nb];
#pragma unroll
                for (int mt = 0; mt < 4; mt++)
                    mma8(c[mt][nt], a[mt], b0, b1);
            }
        }
        __syncthreads();
    }

    // epilogue: scatter rows by rid (each rid written exactly once)
#pragma unroll
    for (int mt = 0; mt < 4; mt++) {
        const int r0 = m0 + wm * 64 + mt * 16 + g;
        const int rlo = (r0 < n_e)     ? g_bucket[off + r0]     : -1;
        const int rhi = (r0 + 8 < n_e) ? g_bucket[off + r0 + 8] : -1;
#pragma unroll
        for (int nt = 0; nt < 4; nt++) {
            const int n = n0 + wn * 32 + nt * 8 + 2 * tig;
            if (rlo >= 0) {
                float2 v; v.x = c[mt][nt][0]; v.y = c[mt][nt][1];
                *(float2*)&g_down[(size_t)rlo * Dd + n] = v;
            }
            if (rhi >= 0) {
                float2 v; v.x = c[mt][nt][2]; v.y = c[mt][nt][3];
                *(float2*)&g_down[(size_t)rhi * Dd + n] = v;
            }
        }
    }
}

// ---------------------- 5. Weighted combine ----------------------
__global__ void combine_kernel(float* __restrict__ out) {
    int i = blockIdx.x * blockDim.x + threadIdx.x;
    const int n4 = Tt * Dd / 4;
    if (i >= n4) return;
    int t = i / (Dd / 4);
    int c = i % (Dd / 4);
    float w0 = g_topw[t * 2 + 0];
    float w1 = g_topw[t * 2 + 1];
    float4 a = ((const float4*)(g_down + (size_t)(t * 2 + 0) * Dd))[c];
    float4 b = ((const float4*)(g_down + (size_t)(t * 2 + 1) * Dd))[c];
    float4 r;
    r.x = w0 * a.x + w1 * b.x;
    r.y = w0 * a.y + w1 * b.y;
    r.z = w0 * a.z + w1 * b.z;
    r.w = w0 * a.w + w1 * b.w;
    ((float4*)out)[i] = r;
}

// ---------------------- launch ----------------------
extern "C" void kernel_launch(void* const* d_in, const int* in_sizes, int n_in,
                              void* d_out, int out_size) {
    const float* x  = (const float*)d_in[0];
    const float* rw = (const float*)d_in[1];
    const float* wg = (const float*)d_in[2];
    const float* wu = (const float*)d_in[3];
    const float* wd = (const float*)d_in[4];
    float* out = (float*)d_out;

    static int configured = 0;
    if (!configured) {
        cudaFuncSetAttribute(gemm1_mma, cudaFuncAttributeMaxDynamicSharedMemorySize, G1_SMEM_BYTES);
        cudaFuncSetAttribute(gemm2_mma, cudaFuncAttributeMaxDynamicSharedMemorySize, G2_SMEM_BYTES);
        configured = 1;
    }

    router_kernel<<<Tt / 8, 256>>>(x, rw);
    compact_kernel<<<1, 256>>>();

    dim3 g1(Ff / 128, NROWS / 128, Ee);   // n fastest -> concurrent m-blocks share weight tiles in L2
    gemm1_mma<<<g1, 256, G1_SMEM_BYTES>>>(x, wg, wu);

    dim3 g2(Dd / 128, NROWS / 128, Ee);
    gemm2_mma<<<g2, 256, G2_SMEM_BYTES>>>(wd);

    combine_kernel<<<(Tt * Dd / 4 + 255) / 256, 256>>>(out);
}

// round 8
// speedup vs baseline: 2.0429x; 1.1346x over previous
#include <cuda_runtime.h>

#define Tt 2048
#define Dd 1024
#define Ff 4096
#define Ee 8
#define NROWS (Tt * 2)

typedef unsigned int u32;

// ---------------- scratch (device globals: allocation-free, graph-safe) ----------------
__device__ u32   g_x_tf[(size_t)Tt * Dd];      // x pre-rounded to tf32 (bit pattern)
__device__ float g_fuse[(size_t)NROWS * Ff];   // compacted, stored tf32-rounded
__device__ float g_down[(size_t)NROWS * Dd];   // indexed by rid = t*2+k
__device__ int   g_bucket[NROWS];
__device__ int   g_offs[Ee + 1];
__device__ float g_topw[NROWS];
__device__ int   g_topidx[NROWS];

// ---------------- helpers ----------------
__device__ __forceinline__ u32 f2tf(float f) {
    u32 u;
    asm("cvt.rna.tf32.f32 %0, %1;" : "=r"(u) : "f"(f));
    return u;
}
__device__ __forceinline__ void mma8(float* c, const u32* a, u32 b0, u32 b1) {
    asm volatile(
        "mma.sync.aligned.m16n8k8.row.col.f32.tf32.tf32.f32 "
        "{%0,%1,%2,%3}, {%4,%5,%6,%7}, {%8,%9}, {%0,%1,%2,%3};"
        : "+f"(c[0]), "+f"(c[1]), "+f"(c[2]), "+f"(c[3])
        : "r"(a[0]), "r"(a[1]), "r"(a[2]), "r"(a[3]), "r"(b0), "r"(b1));
}
__device__ __forceinline__ float silu(float g) { return g / (1.f + __expf(-g)); }

#define CPA(d, s)   asm volatile("cp.async.cg.shared.global [%0], [%1], 16;" :: "r"(d), "l"(s))
#define CPCOMMIT()  asm volatile("cp.async.commit_group;" ::: "memory")
#define CPWAIT(n)   asm volatile("cp.async.wait_group %0;" :: "n"(n) : "memory")

// smem geometry (u32 units). A: [128 m][k32] stride 36 (bank = 4g+tig, distinct).
// B: [k32][128 n] stride 132 (bank = 4tig+g, distinct). Both 16B-aligned rows.
#define AS 36
#define BS 132
#define A_TILE_U32 (128 * AS)   // 4608
#define B_TILE_U32 (32 * BS)    // 4224

// ---------------------- 1. Router ----------------------
__global__ void router_kernel(const float* __restrict__ x, const float* __restrict__ rw) {
    int gw   = (blockIdx.x * blockDim.x + threadIdx.x) >> 5;
    int lane = threadIdx.x & 31;
    if (gw >= Tt) return;
    const float* xr = x + (size_t)gw * Dd;
    float acc[Ee];
#pragma unroll
    for (int e = 0; e < Ee; e++) acc[e] = 0.f;
    for (int d = lane; d < Dd; d += 32) {
        float xv = xr[d];
        const float4* r = (const float4*)(rw + (size_t)d * Ee);
        float4 r0 = r[0], r1 = r[1];
        acc[0] += xv * r0.x; acc[1] += xv * r0.y;
        acc[2] += xv * r0.z; acc[3] += xv * r0.w;
        acc[4] += xv * r1.x; acc[5] += xv * r1.y;
        acc[6] += xv * r1.z; acc[7] += xv * r1.w;
    }
#pragma unroll
    for (int e = 0; e < Ee; e++) {
#pragma unroll
        for (int off = 16; off > 0; off >>= 1)
            acc[e] += __shfl_xor_sync(0xffffffffu, acc[e], off);
    }
    if (lane == 0) {
        int i0 = 0;
#pragma unroll
        for (int e = 1; e < Ee; e++) if (acc[e] > acc[i0]) i0 = e;
        int i1 = (i0 == 0) ? 1 : 0;
#pragma unroll
        for (int e = 0; e < Ee; e++) if (e != i0 && acc[e] > acc[i1]) i1 = e;
        float ex = __expf(acc[i1] - acc[i0]);
        float w0 = 1.f / (1.f + ex);
        g_topidx[gw * 2 + 0] = i0;
        g_topidx[gw * 2 + 1] = i1;
        g_topw[gw * 2 + 0] = w0;
        g_topw[gw * 2 + 1] = ex * w0;
    }
}

// ---------------------- 2. Bucket compaction ----------------------
__global__ void compact_kernel() {
    __shared__ int s_cnt[Ee], s_cur[Ee], s_off[Ee + 1];
    int tid = threadIdx.x;
    if (tid < Ee) { s_cnt[tid] = 0; s_cur[tid] = 0; }
    __syncthreads();
    for (int r = tid; r < NROWS; r += blockDim.x)
        atomicAdd(&s_cnt[g_topidx[r]], 1);
    __syncthreads();
    if (tid == 0) {
        int acc = 0;
        for (int e = 0; e < Ee; e++) { s_off[e] = acc; acc += s_cnt[e]; }
        s_off[Ee] = acc;
        for (int e = 0; e <= Ee; e++) g_offs[e] = s_off[e];
    }
    __syncthreads();
    for (int r = tid; r < NROWS; r += blockDim.x) {
        int e = g_topidx[r];
        int p = atomicAdd(&s_cur[e], 1);
        g_bucket[s_off[e] + p] = r;
    }
}

// ---------------------- 3. x -> tf32 bits ----------------------
__global__ void convert_x_kernel(const float* __restrict__ x) {
    int i = blockIdx.x * blockDim.x + threadIdx.x;
    if (i >= Tt * Dd / 4) return;
    float4 v = ((const float4*)x)[i];
    ((uint4*)g_x_tf)[i] = make_uint4(f2tf(v.x), f2tf(v.y), f2tf(v.z), f2tf(v.w));
}

// ---------------------- 4. GEMM1: cp.async 3-stage, tf32 mma, gate+up + SiLU ----------------------
// block 128M x 128N(gate)+128N(up), K-stage 32, warps 2Mx4N, warp tile 64x32
#define G1_STAGE_U32 (A_TILE_U32 + 2 * B_TILE_U32)         // 13056
#define G1_SMEM_BYTES (3 * G1_STAGE_U32 * 4)               // 156672

__global__ void __launch_bounds__(256, 1) gemm1_mma(
    const float* __restrict__ wg, const float* __restrict__ wu)
{
    extern __shared__ u32 sm[];
    const int e   = blockIdx.z;
    const int off = g_offs[e];
    const int n_e = g_offs[e + 1] - off;
    const int m0  = blockIdx.x * 128;        // m fastest: concurrent CTAs share weight tiles in L2
    if (m0 >= n_e) return;
    const int n0  = blockIdx.y * 128;

    const u32 smb = (u32)__cvta_generic_to_shared(sm);
    const int tid = threadIdx.x, wid = tid >> 5, lane = tid & 31;
    const int g = lane >> 2, tig = lane & 3;
    const int wm = wid >> 2, wn = wid & 3;

    // cp.async loaders: A: 2 thr/row, 64B each; B: 8 thr/k-row, 64B each
    const int arow = tid >> 1, aq = tid & 1;
    const int rid  = g_bucket[off + min(m0 + arow, n_e - 1)] >> 1;
    const char* aSrc = (const char*)(g_x_tf + (size_t)rid * Dd) + aq * 64;
    const int kb = tid >> 3, oct = tid & 7;
    const char* gSrc = (const char*)(wg + (size_t)e * Dd * Ff + (size_t)kb * Ff + n0) + oct * 64;
    const char* uSrc = (const char*)(wu + (size_t)e * Dd * Ff + (size_t)kb * Ff + n0) + oct * 64;
    const u32 aDst = smb + arow * (AS * 4) + aq * 64;
    const u32 gDst = smb + A_TILE_U32 * 4 + kb * (BS * 4) + oct * 64;
    const u32 uDst = gDst + B_TILE_U32 * 4;

    auto issue = [&](int it, int s) {
        const u32 so = s * (G1_STAGE_U32 * 4);
        const char* as = aSrc + (size_t)it * 128;               // 32 floats per stage along K
        const char* gs = gSrc + (size_t)it * (32 * Ff * 4);
        const char* us = uSrc + (size_t)it * (32 * Ff * 4);
#pragma unroll
        for (int j = 0; j < 4; j++) {
            CPA(aDst + so + j * 16, as + j * 16);
            CPA(gDst + so + j * 16, gs + j * 16);
            CPA(uDst + so + j * 16, us + j * 16);
        }
    };

    float cg[4][4][4], cu[4][4][4];
#pragma unroll
    for (int i = 0; i < 4; i++)
#pragma unroll
        for (int j = 0; j < 4; j++)
#pragma unroll
            for (int r = 0; r < 4; r++) { cg[i][j][r] = 0.f; cu[i][j][r] = 0.f; }

    const int NIT = Dd / 32;   // 32
    issue(0, 0); CPCOMMIT();
    issue(1, 1); CPCOMMIT();

#pragma unroll 1
    for (int it = 0; it < NIT; ++it) {
        const int s = it % 3;
        CPWAIT(1);
        __syncthreads();
        if (it + 2 < NIT) issue(it + 2, (it + 2) % 3);
        CPCOMMIT();

        const u32* A  = sm + s * G1_STAGE_U32;
        const u32* Bg = A + A_TILE_U32;
        const u32* Bu = Bg + B_TILE_U32;

#pragma unroll
        for (int ks = 0; ks < 4; ++ks) {
            const int kk = ks * 8;
            u32 a[4][4];
#pragma unroll
            for (int mt = 0; mt < 4; mt++) {
                const int mr = wm * 64 + mt * 16 + g;
                a[mt][0] = A[mr * AS + kk + tig];
                a[mt][1] = A[(mr + 8) * AS + kk + tig];
                a[mt][2] = A[mr * AS + kk + tig + 4];
                a[mt][3] = A[(mr + 8) * AS + kk + tig + 4];
            }
#pragma unroll
            for (int nt = 0; nt < 4; nt++) {
                const int nb = wn * 32 + nt * 8 + g;
                u32 bg0 = f2tf(__uint_as_float(Bg[(kk + tig) * BS + nb]));
                u32 bg1 = f2tf(__uint_as_float(Bg[(kk + tig + 4) * BS + nb]));
                u32 bu0 = f2tf(__uint_as_float(Bu[(kk + tig) * BS + nb]));
                u32 bu1 = f2tf(__uint_as_float(Bu[(kk + tig + 4) * BS + nb]));
#pragma unroll
                for (int mt = 0; mt < 4; mt++) {
                    mma8(cg[mt][nt], a[mt], bg0, bg1);
                    mma8(cu[mt][nt], a[mt], bu0, bu1);
                }
            }
        }
    }

    // epilogue: fuse = silu(gate)*up, stored tf32-rounded (consumed as tf32 by GEMM2)
#pragma unroll
    for (int mt = 0; mt < 4; mt++) {
#pragma unroll
        for (int nt = 0; nt < 4; nt++) {
            const int r0 = wm * 64 + mt * 16 + g;
            const int n  = n0 + wn * 32 + nt * 8 + 2 * tig;
            if (m0 + r0 < n_e) {
                float2 v;
                v.x = __uint_as_float(f2tf(silu(cg[mt][nt][0]) * cu[mt][nt][0]));
                v.y = __uint_as_float(f2tf(silu(cg[mt][nt][1]) * cu[mt][nt][1]));
                *(float2*)&g_fuse[(size_t)(off + m0 + r0) * Ff + n] = v;
            }
            if (m0 + r0 + 8 < n_e) {
                float2 v;
                v.x = __uint_as_float(f2tf(silu(cg[mt][nt][2]) * cu[mt][nt][2]));
                v.y = __uint_as_float(f2tf(silu(cg[mt][nt][3]) * cu[mt][nt][3]));
                *(float2*)&g_fuse[(size_t)(off + m0 + r0 + 8) * Ff + n] = v;
            }
        }
    }
}

// ---------------------- 5. GEMM2: cp.async 4-stage, tf32 mma down-proj ----------------------
#define G2_STAGE_U32 (A_TILE_U32 + B_TILE_U32)             // 8832
#define G2_SMEM_BYTES (4 * G2_STAGE_U32 * 4)               // 141312

__global__ void __launch_bounds__(256, 1) gemm2_mma(const float* __restrict__ wd)
{
    extern __shared__ u32 sm[];
    const int e   = blockIdx.z;
    const int off = g_offs[e];
    const int n_e = g_offs[e + 1] - off;
    const int m0  = blockIdx.x * 128;
    if (m0 >= n_e) return;
    const int n0  = blockIdx.y * 128;

    const u32 smb = (u32)__cvta_generic_to_shared(sm);
    const int tid = threadIdx.x, wid = tid >> 5, lane = tid & 31;
    const int g = lane >> 2, tig = lane & 3;
    const int wm = wid >> 2, wn = wid & 3;

    const int arow = tid >> 1, aq = tid & 1;
    const int ar   = off + min(m0 + arow, n_e - 1);
    const char* aSrc = (const char*)(g_fuse + (size_t)ar * Ff) + aq * 64;
    const int kb = tid >> 3, oct = tid & 7;
    const char* bSrc = (const char*)(wd + (size_t)e * Ff * Dd + (size_t)kb * Dd + n0) + oct * 64;
    const u32 aDst = smb + arow * (AS * 4) + aq * 64;
    const u32 bDst = smb + A_TILE_U32 * 4 + kb * (BS * 4) + oct * 64;

    auto issue = [&](int it, int s) {
        const u32 so = s * (G2_STAGE_U32 * 4);
        const char* as = aSrc + (size_t)it * 128;
        const char* bs = bSrc + (size_t)it * (32 * Dd * 4);
#pragma unroll
        for (int j = 0; j < 4; j++) {
            CPA(aDst + so + j * 16, as + j * 16);
            CPA(bDst + so + j * 16, bs + j * 16);
        }
    };

    float c[4][4][4];
#pragma unroll
    for (int i = 0; i < 4; i++)
#pragma unroll
        for (int j = 0; j < 4; j++)
#pragma unroll
            for (int r = 0; r < 4; r++) c[i][j][r] = 0.f;

    const int NIT = Ff / 32;   // 128
    issue(0, 0); CPCOMMIT();
    issue(1, 1); CPCOMMIT();
    issue(2, 2); CPCOMMIT();

#pragma unroll 1
    for (int it = 0; it < NIT; ++it) {
        const int s = it & 3;
        CPWAIT(2);
        __syncthreads();
        if (it + 3 < NIT) issue(it + 3, (it + 3) & 3);
        CPCOMMIT();

        const u32* A = sm + s * G2_STAGE_U32;
        const u32* B = A + A_TILE_U32;

#pragma unroll
        for (int ks = 0; ks < 4; ++ks) {
            const int kk = ks * 8;
            u32 a[4][4];
#pragma unroll
            for (int mt = 0; mt < 4; mt++) {
                const int mr = wm * 64 + mt * 16 + g;
                a[mt][0] = A[mr * AS + kk + tig];
                a[mt][1] = A[(mr + 8) * AS + kk + tig];
                a[mt][2] = A[mr * AS + kk + tig + 4];
                a[mt][3] = A[(mr + 8) * AS + kk + tig + 4];
            }
#pragma unroll
            for (int nt = 0; nt < 4; nt++) {
                const int nb = wn * 32 + nt * 8 + g;
                u32 b0 = f2tf(__uint_as_float(B[(kk + tig) * BS + nb]));
                u32 b1 = f2tf(__uint_as_float(B[(kk + tig + 4) * BS + nb]));
#pragma unroll
                for (int mt = 0; mt < 4; mt++)
                    mma8(c[mt][nt], a[mt], b0, b1);
            }
        }
    }

    // epilogue: scatter rows by rid (each rid written exactly once)
#pragma unroll
    for (int mt = 0; mt < 4; mt++) {
        const int r0 = m0 + wm * 64 + mt * 16 + g;
        const int rlo = (r0 < n_e)     ? g_bucket[off + r0]     : -1;
        const int rhi = (r0 + 8 < n_e) ? g_bucket[off + r0 + 8] : -1;
#pragma unroll
        for (int nt = 0; nt < 4; nt++) {
            const int n = n0 + wn * 32 + nt * 8 + 2 * tig;
            if (rlo >= 0) {
                float2 v; v.x = c[mt][nt][0]; v.y = c[mt][nt][1];
                *(float2*)&g_down[(size_t)rlo * Dd + n] = v;
            }
            if (rhi >= 0) {
                float2 v; v.x = c[mt][nt][2]; v.y = c[mt][nt][3];
                *(float2*)&g_down[(size_t)rhi * Dd + n] = v;
            }
        }
    }
}

// ---------------------- 6. Weighted combine ----------------------
__global__ void combine_kernel(float* __restrict__ out) {
    int i = blockIdx.x * blockDim.x + threadIdx.x;
    const int n4 = Tt * Dd / 4;
    if (i >= n4) return;
    int t = i / (Dd / 4);
    int c = i % (Dd / 4);
    float w0 = g_topw[t * 2 + 0];
    float w1 = g_topw[t * 2 + 1];
    float4 a = ((const float4*)(g_down + (size_t)(t * 2 + 0) * Dd))[c];
    float4 b = ((const float4*)(g_down + (size_t)(t * 2 + 1) * Dd))[c];
    float4 r;
    r.x = w0 * a.x + w1 * b.x;
    r.y = w0 * a.y + w1 * b.y;
    r.z = w0 * a.z + w1 * b.z;
    r.w = w0 * a.w + w1 * b.w;
    ((float4*)out)[i] = r;
}

// ---------------------- launch ----------------------
extern "C" void kernel_launch(void* const* d_in, const int* in_sizes, int n_in,
                              void* d_out, int out_size) {
    const float* x  = (const float*)d_in[0];
    const float* rw = (const float*)d_in[1];
    const float* wg = (const float*)d_in[2];
    const float* wu = (const float*)d_in[3];
    const float* wd = (const float*)d_in[4];
    float* out = (float*)d_out;

    static int configured = 0;
    if (!configured) {
        cudaFuncSetAttribute(gemm1_mma, cudaFuncAttributeMaxDynamicSharedMemorySize, G1_SMEM_BYTES);
        cudaFuncSetAttribute(gemm2_mma, cudaFuncAttributeMaxDynamicSharedMemorySize, G2_SMEM_BYTES);
        configured = 1;
    }

    router_kernel<<<Tt / 8, 256>>>(x, rw);
    compact_kernel<<<1, 256>>>();
    convert_x_kernel<<<(Tt * Dd / 4 + 255) / 256, 256>>>(x);

    dim3 g1(NROWS / 128, Ff / 128, Ee);   // m fastest: weight-tile L2 reuse across concurrent CTAs
    gemm1_mma<<<g1, 256, G1_SMEM_BYTES>>>(wg, wu);

    dim3 g2(NROWS / 128, Dd / 128, Ee);
    gemm2_mma<<<g2, 256, G2_SMEM_BYTES>>>(wd);

    combine_kernel<<<(Tt * Dd / 4 + 255) / 256, 256>>>(out);
}

// round 9
// speedup vs baseline: 2.2746x; 1.1134x over previous
#include <cuda_runtime.h>

#define Tt 2048
#define Dd 1024
#define Ff 4096
#define Ee 8
#define NROWS (Tt * 2)

typedef unsigned int u32;

// ---------------- scratch (device globals: allocation-free, graph-safe) ----------------
__device__ u32   g_x_tf[(size_t)Tt * Dd];      // x pre-rounded to tf32 (bit pattern)
__device__ float g_fuse[(size_t)NROWS * Ff];   // compacted, stored tf32-rounded
__device__ float g_down[(size_t)NROWS * Dd];   // indexed by rid = t*2+k
__device__ int   g_bucket[NROWS];
__device__ int   g_offs[Ee + 1];
__device__ float g_topw[NROWS];
__device__ int   g_topidx[NROWS];

// ---------------- helpers ----------------
__device__ __forceinline__ u32 f2tf(float f) {
    u32 u;
    asm("cvt.rna.tf32.f32 %0, %1;" : "=r"(u) : "f"(f));
    return u;
}
__device__ __forceinline__ void mma8(float* c, const u32* a, u32 b0, u32 b1) {
    asm volatile(
        "mma.sync.aligned.m16n8k8.row.col.f32.tf32.tf32.f32 "
        "{%0,%1,%2,%3}, {%4,%5,%6,%7}, {%8,%9}, {%0,%1,%2,%3};"
        : "+f"(c[0]), "+f"(c[1]), "+f"(c[2]), "+f"(c[3])
        : "r"(a[0]), "r"(a[1]), "r"(a[2]), "r"(a[3]), "r"(b0), "r"(b1));
}
__device__ __forceinline__ float silu(float g) { return g / (1.f + __expf(-g)); }

#define CPA(d, s)   asm volatile("cp.async.cg.shared.global [%0], [%1], 16;" :: "r"(d), "l"(s))
#define CPCOMMIT()  asm volatile("cp.async.commit_group;" ::: "memory")
#define CPWAIT(n)   asm volatile("cp.async.wait_group %0;" :: "n"(n) : "memory")

// smem geometry (u32 units). A: [128 m][k32] stride 36 (bank = 4g+tig -> conflict-free).
// B: [k32][128 n] stride 132.
#define AS 36
#define BS 132
#define A_TILE_U32 (128 * AS)   // 4608
#define B_TILE_U32 (32 * BS)    // 4224

// ---------------------- 1. Router ----------------------
__global__ void router_kernel(const float* __restrict__ x, const float* __restrict__ rw) {
    int gw   = (blockIdx.x * blockDim.x + threadIdx.x) >> 5;
    int lane = threadIdx.x & 31;
    if (gw >= Tt) return;
    const float* xr = x + (size_t)gw * Dd;
    float acc[Ee];
#pragma unroll
    for (int e = 0; e < Ee; e++) acc[e] = 0.f;
    for (int d = lane; d < Dd; d += 32) {
        float xv = xr[d];
        const float4* r = (const float4*)(rw + (size_t)d * Ee);
        float4 r0 = r[0], r1 = r[1];
        acc[0] += xv * r0.x; acc[1] += xv * r0.y;
        acc[2] += xv * r0.z; acc[3] += xv * r0.w;
        acc[4] += xv * r1.x; acc[5] += xv * r1.y;
        acc[6] += xv * r1.z; acc[7] += xv * r1.w;
    }
#pragma unroll
    for (int e = 0; e < Ee; e++) {
#pragma unroll
        for (int off = 16; off > 0; off >>= 1)
            acc[e] += __shfl_xor_sync(0xffffffffu, acc[e], off);
    }
    if (lane == 0) {
        int i0 = 0;
#pragma unroll
        for (int e = 1; e < Ee; e++) if (acc[e] > acc[i0]) i0 = e;
        int i1 = (i0 == 0) ? 1 : 0;
#pragma unroll
        for (int e = 0; e < Ee; e++) if (e != i0 && acc[e] > acc[i1]) i1 = e;
        float ex = __expf(acc[i1] - acc[i0]);
        float w0 = 1.f / (1.f + ex);
        g_topidx[gw * 2 + 0] = i0;
        g_topidx[gw * 2 + 1] = i1;
        g_topw[gw * 2 + 0] = w0;
        g_topw[gw * 2 + 1] = ex * w0;
    }
}

// ---------------------- 2. Bucket compaction ----------------------
__global__ void compact_kernel() {
    __shared__ int s_cnt[Ee], s_cur[Ee], s_off[Ee + 1];
    int tid = threadIdx.x;
    if (tid < Ee) { s_cnt[tid] = 0; s_cur[tid] = 0; }
    __syncthreads();
    for (int r = tid; r < NROWS; r += blockDim.x)
        atomicAdd(&s_cnt[g_topidx[r]], 1);
    __syncthreads();
    if (tid == 0) {
        int acc = 0;
        for (int e = 0; e < Ee; e++) { s_off[e] = acc; acc += s_cnt[e]; }
        s_off[Ee] = acc;
        for (int e = 0; e <= Ee; e++) g_offs[e] = s_off[e];
    }
    __syncthreads();
    for (int r = tid; r < NROWS; r += blockDim.x) {
        int e = g_topidx[r];
        int p = atomicAdd(&s_cur[e], 1);
        g_bucket[s_off[e] + p] = r;
    }
}

// ---------------------- 3. x -> tf32 bits ----------------------
__global__ void convert_x_kernel(const float* __restrict__ x) {
    int i = blockIdx.x * blockDim.x + threadIdx.x;
    if (i >= Tt * Dd / 4) return;
    float4 v = ((const float4*)x)[i];
    ((uint4*)g_x_tf)[i] = make_uint4(f2tf(v.x), f2tf(v.y), f2tf(v.z), f2tf(v.w));
}

// ---------------------- 4. GEMM1: 512 thr, 16 warps, cp.async 3-stage ----------------------
// block 128M x 128N(gate)+128N(up), K-stage 32, warps 4Mx4N, warp tile 32x32
#define G1_STAGE_U32 (A_TILE_U32 + 2 * B_TILE_U32)         // 13056
#define G1_SMEM_BYTES (3 * G1_STAGE_U32 * 4)               // 156672

__global__ void __launch_bounds__(512, 1) gemm1_mma(
    const float* __restrict__ wg, const float* __restrict__ wu)
{
    extern __shared__ u32 sm[];
    const int e   = blockIdx.z;
    const int off = g_offs[e];
    const int n_e = g_offs[e + 1] - off;
    const int m0  = blockIdx.x * 128;        // m fastest: weight-tile L2 reuse
    if (m0 >= n_e) return;
    const int n0  = blockIdx.y * 128;

    const u32 smb = (u32)__cvta_generic_to_shared(sm);
    const int tid = threadIdx.x, wid = tid >> 5, lane = tid & 31;
    const int g = lane >> 2, tig = lane & 3;
    const int wm = wid >> 2, wn = wid & 3;

    // cp.async loaders (512 thr): A: 4 thr/row, 32B each; B: 16 thr/k-row, 32B each
    const int arow = tid >> 2, aq = tid & 3;
    const int rid  = g_bucket[off + min(m0 + arow, n_e - 1)] >> 1;
    const char* aSrc = (const char*)(g_x_tf + (size_t)rid * Dd) + aq * 32;
    const int kb = tid >> 4, oct = tid & 15;
    const char* gSrc = (const char*)(wg + (size_t)e * Dd * Ff + (size_t)kb * Ff + n0) + oct * 32;
    const char* uSrc = (const char*)(wu + (size_t)e * Dd * Ff + (size_t)kb * Ff + n0) + oct * 32;
    const u32 aDst = smb + arow * (AS * 4) + aq * 32;
    const u32 gDst = smb + A_TILE_U32 * 4 + kb * (BS * 4) + oct * 32;
    const u32 uDst = gDst + B_TILE_U32 * 4;

    auto issue = [&](int it, int s) {
        const u32 so = s * (G1_STAGE_U32 * 4);
        const char* as = aSrc + (size_t)it * 128;               // 32 floats along K
        const char* gs = gSrc + (size_t)it * (32 * Ff * 4);
        const char* us = uSrc + (size_t)it * (32 * Ff * 4);
        CPA(aDst + so,      as);      CPA(aDst + so + 16, as + 16);
        CPA(gDst + so,      gs);      CPA(gDst + so + 16, gs + 16);
        CPA(uDst + so,      us);      CPA(uDst + so + 16, us + 16);
    };

    float cg[2][4][4], cu[2][4][4];
#pragma unroll
    for (int i = 0; i < 2; i++)
#pragma unroll
        for (int j = 0; j < 4; j++)
#pragma unroll
            for (int r = 0; r < 4; r++) { cg[i][j][r] = 0.f; cu[i][j][r] = 0.f; }

    const int NIT = Dd / 32;   // 32
    issue(0, 0); CPCOMMIT();
    issue(1, 1); CPCOMMIT();

#pragma unroll 1
    for (int it = 0; it < NIT; ++it) {
        const int s = it % 3;
        CPWAIT(1);
        __syncthreads();
        if (it + 2 < NIT) issue(it + 2, (it + 2) % 3);
        CPCOMMIT();

        const u32* A  = sm + s * G1_STAGE_U32;
        const u32* Bg = A + A_TILE_U32;
        const u32* Bu = Bg + B_TILE_U32;

#pragma unroll
        for (int ks = 0; ks < 4; ++ks) {
            const int kk = ks * 8;
            u32 a[2][4];
#pragma unroll
            for (int mt = 0; mt < 2; mt++) {
                const int mr = wm * 32 + mt * 16 + g;
                a[mt][0] = A[mr * AS + kk + tig];
                a[mt][1] = A[(mr + 8) * AS + kk + tig];
                a[mt][2] = A[mr * AS + kk + tig + 4];
                a[mt][3] = A[(mr + 8) * AS + kk + tig + 4];
            }
#pragma unroll
            for (int nt = 0; nt < 4; nt++) {
                const int nb = wn * 32 + nt * 8 + g;
                u32 bg0 = f2tf(__uint_as_float(Bg[(kk + tig) * BS + nb]));
                u32 bg1 = f2tf(__uint_as_float(Bg[(kk + tig + 4) * BS + nb]));
                u32 bu0 = f2tf(__uint_as_float(Bu[(kk + tig) * BS + nb]));
                u32 bu1 = f2tf(__uint_as_float(Bu[(kk + tig + 4) * BS + nb]));
#pragma unroll
                for (int mt = 0; mt < 2; mt++) {
                    mma8(cg[mt][nt], a[mt], bg0, bg1);
                    mma8(cu[mt][nt], a[mt], bu0, bu1);
                }
            }
        }
    }

    // epilogue: fuse = silu(gate)*up, stored tf32-rounded (consumed as tf32 by GEMM2)
#pragma unroll
    for (int mt = 0; mt < 2; mt++) {
#pragma unroll
        for (int nt = 0; nt < 4; nt++) {
            const int r0 = wm * 32 + mt * 16 + g;
            const int n  = n0 + wn * 32 + nt * 8 + 2 * tig;
            if (m0 + r0 < n_e) {
                float2 v;
                v.x = __uint_as_float(f2tf(silu(cg[mt][nt][0]) * cu[mt][nt][0]));
                v.y = __uint_as_float(f2tf(silu(cg[mt][nt][1]) * cu[mt][nt][1]));
                *(float2*)&g_fuse[(size_t)(off + m0 + r0) * Ff + n] = v;
            }
            if (m0 + r0 + 8 < n_e) {
                float2 v;
                v.x = __uint_as_float(f2tf(silu(cg[mt][nt][2]) * cu[mt][nt][2]));
                v.y = __uint_as_float(f2tf(silu(cg[mt][nt][3]) * cu[mt][nt][3]));
                *(float2*)&g_fuse[(size_t)(off + m0 + r0 + 8) * Ff + n] = v;
            }
        }
    }
}

// ---------------------- 5. GEMM2: 512 thr, 16 warps, cp.async 4-stage ----------------------
#define G2_STAGE_U32 (A_TILE_U32 + B_TILE_U32)             // 8832
#define G2_SMEM_BYTES (4 * G2_STAGE_U32 * 4)               // 141312

__global__ void __launch_bounds__(512, 1) gemm2_mma(const float* __restrict__ wd)
{
    extern __shared__ u32 sm[];
    const int e   = blockIdx.z;
    const int off = g_offs[e];
    const int n_e = g_offs[e + 1] - off;
    const int m0  = blockIdx.x * 128;
    if (m0 >= n_e) return;
    const int n0  = blockIdx.y * 128;

    const u32 smb = (u32)__cvta_generic_to_shared(sm);
    const int tid = threadIdx.x, wid = tid >> 5, lane = tid & 31;
    const int g = lane >> 2, tig = lane & 3;
    const int wm = wid >> 2, wn = wid & 3;

    const int arow = tid >> 2, aq = tid & 3;
    const int ar   = off + min(m0 + arow, n_e - 1);
    const char* aSrc = (const char*)(g_fuse + (size_t)ar * Ff) + aq * 32;
    const int kb = tid >> 4, oct = tid & 15;
    const char* bSrc = (const char*)(wd + (size_t)e * Ff * Dd + (size_t)kb * Dd + n0) + oct * 32;
    const u32 aDst = smb + arow * (AS * 4) + aq * 32;
    const u32 bDst = smb + A_TILE_U32 * 4 + kb * (BS * 4) + oct * 32;

    auto issue = [&](int it, int s) {
        const u32 so = s * (G2_STAGE_U32 * 4);
        const char* as = aSrc + (size_t)it * 128;
        const char* bs = bSrc + (size_t)it * (32 * Dd * 4);
        CPA(aDst + so,      as);      CPA(aDst + so + 16, as + 16);
        CPA(bDst + so,      bs);      CPA(bDst + so + 16, bs + 16);
    };

    float c[2][4][4];
#pragma unroll
    for (int i = 0; i < 2; i++)
#pragma unroll
        for (int j = 0; j < 4; j++)
#pragma unroll
            for (int r = 0; r < 4; r++) c[i][j][r] = 0.f;

    const int NIT = Ff / 32;   // 128
    issue(0, 0); CPCOMMIT();
    issue(1, 1); CPCOMMIT();
    issue(2, 2); CPCOMMIT();

#pragma unroll 1
    for (int it = 0; it < NIT; ++it) {
        const int s = it & 3;
        CPWAIT(2);
        __syncthreads();
        if (it + 3 < NIT) issue(it + 3, (it + 3) & 3);
        CPCOMMIT();

        const u32* A = sm + s * G2_STAGE_U32;
        const u32* B = A + A_TILE_U32;

#pragma unroll
        for (int ks = 0; ks < 4; ++ks) {
            const int kk = ks * 8;
            u32 a[2][4];
#pragma unroll
            for (int mt = 0; mt < 2; mt++) {
                const int mr = wm * 32 + mt * 16 + g;
                a[mt][0] = A[mr * AS + kk + tig];
                a[mt][1] = A[(mr + 8) * AS + kk + tig];
                a[mt][2] = A[mr * AS + kk + tig + 4];
                a[mt][3] = A[(mr + 8) * AS + kk + tig + 4];
            }
#pragma unroll
            for (int nt = 0; nt < 4; nt++) {
                const int nb = wn * 32 + nt * 8 + g;
                u32 b0 = f2tf(__uint_as_float(B[(kk + tig) * BS + nb]));
                u32 b1 = f2tf(__uint_as_float(B[(kk + tig + 4) * BS + nb]));
#pragma unroll
                for (int mt = 0; mt < 2; mt++)
                    mma8(c[mt][nt], a[mt], b0, b1);
            }
        }
    }

    // epilogue: scatter rows by rid (each rid written exactly once)
#pragma unroll
    for (int mt = 0; mt < 2; mt++) {
        const int r0 = m0 + wm * 32 + mt * 16 + g;
        const int rlo = (r0 < n_e)     ? g_bucket[off + r0]     : -1;
        const int rhi = (r0 + 8 < n_e) ? g_bucket[off + r0 + 8] : -1;
#pragma unroll
        for (int nt = 0; nt < 4; nt++) {
            const int n = n0 + wn * 32 + nt * 8 + 2 * tig;
            if (rlo >= 0) {
                float2 v; v.x = c[mt][nt][0]; v.y = c[mt][nt][1];
                *(float2*)&g_down[(size_t)rlo * Dd + n] = v;
            }
            if (rhi >= 0) {
                float2 v; v.x = c[mt][nt][2]; v.y = c[mt][nt][3];
                *(float2*)&g_down[(size_t)rhi * Dd + n] = v;
            }
        }
    }
}

// ---------------------- 6. Weighted combine ----------------------
__global__ void combine_kernel(float* __restrict__ out) {
    int i = blockIdx.x * blockDim.x + threadIdx.x;
    const int n4 = Tt * Dd / 4;
    if (i >= n4) return;
    int t = i / (Dd / 4);
    int c = i % (Dd / 4);
    float w0 = g_topw[t * 2 + 0];
    float w1 = g_topw[t * 2 + 1];
    float4 a = ((const float4*)(g_down + (size_t)(t * 2 + 0) * Dd))[c];
    float4 b = ((const float4*)(g_down + (size_t)(t * 2 + 1) * Dd))[c];
    float4 r;
    r.x = w0 * a.x + w1 * b.x;
    r.y = w0 * a.y + w1 * b.y;
    r.z = w0 * a.z + w1 * b.z;
    r.w = w0 * a.w + w1 * b.w;
    ((float4*)out)[i] = r;
}

// ---------------------- launch ----------------------
extern "C" void kernel_launch(void* const* d_in, const int* in_sizes, int n_in,
                              void* d_out, int out_size) {
    const float* x  = (const float*)d_in[0];
    const float* rw = (const float*)d_in[1];
    const float* wg = (const float*)d_in[2];
    const float* wu = (const float*)d_in[3];
    const float* wd = (const float*)d_in[4];
    float* out = (float*)d_out;

    static int configured = 0;
    if (!configured) {
        cudaFuncSetAttribute(gemm1_mma, cudaFuncAttributeMaxDynamicSharedMemorySize, G1_SMEM_BYTES);
        cudaFuncSetAttribute(gemm2_mma, cudaFuncAttributeMaxDynamicSharedMemorySize, G2_SMEM_BYTES);
        configured = 1;
    }

    router_kernel<<<Tt / 8, 256>>>(x, rw);
    compact_kernel<<<1, 256>>>();
    convert_x_kernel<<<(Tt * Dd / 4 + 255) / 256, 256>>>(x);

    dim3 g1(NROWS / 128, Ff / 128, Ee);   // m fastest: weight-tile L2 reuse
    gemm1_mma<<<g1, 512, G1_SMEM_BYTES>>>(wg, wu);

    dim3 g2(NROWS / 128, Dd / 128, Ee);
    gemm2_mma<<<g2, 512, G2_SMEM_BYTES>>>(wd);

    combine_kernel<<<(Tt * Dd / 4 + 255) / 256, 256>>>(out);
}

// round 10
// speedup vs baseline: 2.4708x; 1.0863x over previous
#include <cuda_runtime.h>

#define Tt 2048
#define Dd 1024
#define Ff 4096
#define Ee 8
#define NROWS (Tt * 2)

typedef unsigned int u32;

// ---------------- scratch (device globals: allocation-free, graph-safe) ----------------
__device__ u32   g_x_tf[(size_t)Tt * Dd];      // x pre-rounded to tf32 (bit pattern)
__device__ float g_fuse[(size_t)NROWS * Ff];   // compacted, stored tf32-rounded
__device__ float g_down[(size_t)NROWS * Dd];   // indexed by rid = t*2+k
__device__ int   g_bucket[NROWS];
__device__ int   g_offs[Ee + 1];
__device__ float g_topw[NROWS];
__device__ int   g_topidx[NROWS];

// ---------------- helpers ----------------
__device__ __forceinline__ u32 f2tf(float f) {
    u32 u;
    asm("cvt.rna.tf32.f32 %0, %1;" : "=r"(u) : "f"(f));
    return u;
}
__device__ __forceinline__ void mma8(float* c, const u32* a, u32 b0, u32 b1) {
    asm volatile(
        "mma.sync.aligned.m16n8k8.row.col.f32.tf32.tf32.f32 "
        "{%0,%1,%2,%3}, {%4,%5,%6,%7}, {%8,%9}, {%0,%1,%2,%3};"
        : "+f"(c[0]), "+f"(c[1]), "+f"(c[2]), "+f"(c[3])
        : "r"(a[0]), "r"(a[1]), "r"(a[2]), "r"(a[3]), "r"(b0), "r"(b1));
}
// tf32 A-fragment via ldmatrix: 4 8x8(b32-as-2xb16) tiles; reg j of lane i = Mat_j[i/4][i%4]
__device__ __forceinline__ void ldsm4(u32* r, u32 addr) {
    asm volatile("ldmatrix.sync.aligned.m8n8.x4.shared.b16 {%0,%1,%2,%3}, [%4];"
                 : "=r"(r[0]), "=r"(r[1]), "=r"(r[2]), "=r"(r[3]) : "r"(addr));
}
__device__ __forceinline__ float silu(float g) { return g / (1.f + __expf(-g)); }

#define CPA(d, s)   asm volatile("cp.async.cg.shared.global [%0], [%1], 16;" :: "r"(d), "l"(s))
#define CPCOMMIT()  asm volatile("cp.async.commit_group;" ::: "memory")
#define CPWAIT(n)   asm volatile("cp.async.wait_group %0;" :: "n"(n) : "memory")

// smem geometry (u32 units).
// A: [128 m][k32] stride 36  -> LDS bank = (4g+tig) = lane  (conflict-free); rows 144B (16B-mult)
// B: [k32][128 n] stride 136 -> LDS bank = (8tig+g)         (conflict-free; 132 had 2-way conflicts)
#define AS 36
#define BS 136
#define A_TILE_U32 (128 * AS)   // 4608
#define B_TILE_U32 (32 * BS)    // 4352

// ---------------------- 1. Router ----------------------
__global__ void router_kernel(const float* __restrict__ x, const float* __restrict__ rw) {
    int gw   = (blockIdx.x * blockDim.x + threadIdx.x) >> 5;
    int lane = threadIdx.x & 31;
    if (gw >= Tt) return;
    const float* xr = x + (size_t)gw * Dd;
    float acc[Ee];
#pragma unroll
    for (int e = 0; e < Ee; e++) acc[e] = 0.f;
    for (int d = lane; d < Dd; d += 32) {
        float xv = xr[d];
        const float4* r = (const float4*)(rw + (size_t)d * Ee);
        float4 r0 = r[0], r1 = r[1];
        acc[0] += xv * r0.x; acc[1] += xv * r0.y;
        acc[2] += xv * r0.z; acc[3] += xv * r0.w;
        acc[4] += xv * r1.x; acc[5] += xv * r1.y;
        acc[6] += xv * r1.z; acc[7] += xv * r1.w;
    }
#pragma unroll
    for (int e = 0; e < Ee; e++) {
#pragma unroll
        for (int off = 16; off > 0; off >>= 1)
            acc[e] += __shfl_xor_sync(0xffffffffu, acc[e], off);
    }
    if (lane == 0) {
        int i0 = 0;
#pragma unroll
        for (int e = 1; e < Ee; e++) if (acc[e] > acc[i0]) i0 = e;
        int i1 = (i0 == 0) ? 1 : 0;
#pragma unroll
        for (int e = 0; e < Ee; e++) if (e != i0 && acc[e] > acc[i1]) i1 = e;
        float ex = __expf(acc[i1] - acc[i0]);
        float w0 = 1.f / (1.f + ex);
        g_topidx[gw * 2 + 0] = i0;
        g_topidx[gw * 2 + 1] = i1;
        g_topw[gw * 2 + 0] = w0;
        g_topw[gw * 2 + 1] = ex * w0;
    }
}

// ---------------------- 2. Bucket compaction ----------------------
__global__ void compact_kernel() {
    __shared__ int s_cnt[Ee], s_cur[Ee], s_off[Ee + 1];
    int tid = threadIdx.x;
    if (tid < Ee) { s_cnt[tid] = 0; s_cur[tid] = 0; }
    __syncthreads();
    for (int r = tid; r < NROWS; r += blockDim.x)
        atomicAdd(&s_cnt[g_topidx[r]], 1);
    __syncthreads();
    if (tid == 0) {
        int acc = 0;
        for (int e = 0; e < Ee; e++) { s_off[e] = acc; acc += s_cnt[e]; }
        s_off[Ee] = acc;
        for (int e = 0; e <= Ee; e++) g_offs[e] = s_off[e];
    }
    __syncthreads();
    for (int r = tid; r < NROWS; r += blockDim.x) {
        int e = g_topidx[r];
        int p = atomicAdd(&s_cur[e], 1);
        g_bucket[s_off[e] + p] = r;
    }
}

// ---------------------- 3. x -> tf32 bits ----------------------
__global__ void convert_x_kernel(const float* __restrict__ x) {
    int i = blockIdx.x * blockDim.x + threadIdx.x;
    if (i >= Tt * Dd / 4) return;
    float4 v = ((const float4*)x)[i];
    ((uint4*)g_x_tf)[i] = make_uint4(f2tf(v.x), f2tf(v.y), f2tf(v.z), f2tf(v.w));
}

// ---------------------- 4. GEMM1: 512 thr, 16 warps, cp.async 4-stage, ldmatrix A ----------------------
// block 128M x 128N(gate)+128N(up), K-stage 32, warps 4Mx4N, warp tile 32x32
#define G1_STAGE_U32 (A_TILE_U32 + 2 * B_TILE_U32)         // 13312
#define G1_STAGES 4
#define G1_SMEM_BYTES (G1_STAGES * G1_STAGE_U32 * 4)       // 212992

__global__ void __launch_bounds__(512, 1) gemm1_mma(
    const float* __restrict__ wg, const float* __restrict__ wu)
{
    extern __shared__ u32 sm[];
    const int e   = blockIdx.z;
    const int off = g_offs[e];
    const int n_e = g_offs[e + 1] - off;
    const int m0  = blockIdx.x * 128;        // m fastest: weight-tile L2 reuse
    if (m0 >= n_e) return;
    const int n0  = blockIdx.y * 128;

    const u32 smb = (u32)__cvta_generic_to_shared(sm);
    const int tid = threadIdx.x, wid = tid >> 5, lane = tid & 31;
    const int g = lane >> 2, tig = lane & 3;
    const int wm = wid >> 2, wn = wid & 3;

    // ldmatrix per-lane source offset (u32 units): lanes 0-7 -> Mat0 rows, 8-15 Mat1, 16-23 Mat2, 24-31 Mat3
    const int lmat = lane >> 3, lrow = lane & 7;
    const int aoff = ((lmat & 1) * 8 + lrow) * AS + (lmat >> 1) * 4;

    // cp.async loaders (512 thr): A: 4 thr/row, 32B each; B: 16 thr/k-row, 32B each
    const int arow = tid >> 2, aq = tid & 3;
    const int rid  = g_bucket[off + min(m0 + arow, n_e - 1)] >> 1;
    const char* aSrc = (const char*)(g_x_tf + (size_t)rid * Dd) + aq * 32;
    const int kb = tid >> 4, oct = tid & 15;
    const char* gSrc = (const char*)(wg + (size_t)e * Dd * Ff + (size_t)kb * Ff + n0) + oct * 32;
    const char* uSrc = (const char*)(wu + (size_t)e * Dd * Ff + (size_t)kb * Ff + n0) + oct * 32;
    const u32 aDst = smb + arow * (AS * 4) + aq * 32;
    const u32 gDst = smb + A_TILE_U32 * 4 + kb * (BS * 4) + oct * 32;
    const u32 uDst = gDst + B_TILE_U32 * 4;

    auto issue = [&](int it, int s) {
        const u32 so = s * (G1_STAGE_U32 * 4);
        const char* as = aSrc + (size_t)it * 128;               // 32 floats along K
        const char* gs = gSrc + (size_t)it * (32 * Ff * 4);
        const char* us = uSrc + (size_t)it * (32 * Ff * 4);
        CPA(aDst + so,      as);      CPA(aDst + so + 16, as + 16);
        CPA(gDst + so,      gs);      CPA(gDst + so + 16, gs + 16);
        CPA(uDst + so,      us);      CPA(uDst + so + 16, us + 16);
    };

    float cg[2][4][4], cu[2][4][4];
#pragma unroll
    for (int i = 0; i < 2; i++)
#pragma unroll
        for (int j = 0; j < 4; j++)
#pragma unroll
            for (int r = 0; r < 4; r++) { cg[i][j][r] = 0.f; cu[i][j][r] = 0.f; }

    const int NIT = Dd / 32;   // 32
    issue(0, 0); CPCOMMIT();
    issue(1, 1); CPCOMMIT();
    issue(2, 2); CPCOMMIT();

#pragma unroll 1
    for (int it = 0; it < NIT; ++it) {
        const int s = it & 3;
        CPWAIT(2);
        __syncthreads();
        if (it + 3 < NIT) issue(it + 3, (it + 3) & 3);
        CPCOMMIT();

        const u32 Ab = smb + s * (G1_STAGE_U32 * 4) + (wm * 32 * AS + aoff) * 4;
        const u32* A  = sm + s * G1_STAGE_U32;
        const u32* Bg = A + A_TILE_U32;
        const u32* Bu = Bg + B_TILE_U32;

#pragma unroll
        for (int ks = 0; ks < 4; ++ks) {
            const int kk = ks * 8;
            u32 a[2][4];
            ldsm4(a[0], Ab + kk * 4);
            ldsm4(a[1], Ab + (16 * AS + kk) * 4);
#pragma unroll
            for (int nt = 0; nt < 4; nt++) {
                const int nb = wn * 32 + nt * 8 + g;
                u32 bg0 = f2tf(__uint_as_float(Bg[(kk + tig) * BS + nb]));
                u32 bg1 = f2tf(__uint_as_float(Bg[(kk + tig + 4) * BS + nb]));
                u32 bu0 = f2tf(__uint_as_float(Bu[(kk + tig) * BS + nb]));
                u32 bu1 = f2tf(__uint_as_float(Bu[(kk + tig + 4) * BS + nb]));
#pragma unroll
                for (int mt = 0; mt < 2; mt++) {
                    mma8(cg[mt][nt], a[mt], bg0, bg1);
                    mma8(cu[mt][nt], a[mt], bu0, bu1);
                }
            }
        }
    }

    // epilogue: fuse = silu(gate)*up, stored tf32-rounded (consumed as tf32 by GEMM2)
#pragma unroll
    for (int mt = 0; mt < 2; mt++) {
#pragma unroll
        for (int nt = 0; nt < 4; nt++) {
            const int r0 = wm * 32 + mt * 16 + g;
            const int n  = n0 + wn * 32 + nt * 8 + 2 * tig;
            if (m0 + r0 < n_e) {
                float2 v;
                v.x = __uint_as_float(f2tf(silu(cg[mt][nt][0]) * cu[mt][nt][0]));
                v.y = __uint_as_float(f2tf(silu(cg[mt][nt][1]) * cu[mt][nt][1]));
                *(float2*)&g_fuse[(size_t)(off + m0 + r0) * Ff + n] = v;
            }
            if (m0 + r0 + 8 < n_e) {
                float2 v;
                v.x = __uint_as_float(f2tf(silu(cg[mt][nt][2]) * cu[mt][nt][2]));
                v.y = __uint_as_float(f2tf(silu(cg[mt][nt][3]) * cu[mt][nt][3]));
                *(float2*)&g_fuse[(size_t)(off + m0 + r0 + 8) * Ff + n] = v;
            }
        }
    }
}

// ---------------------- 5. GEMM2: 512 thr, 16 warps, cp.async 4-stage, ldmatrix A ----------------------
#define G2_STAGE_U32 (A_TILE_U32 + B_TILE_U32)             // 8960
#define G2_SMEM_BYTES (4 * G2_STAGE_U32 * 4)               // 143360

__global__ void __launch_bounds__(512, 1) gemm2_mma(const float* __restrict__ wd)
{
    extern __shared__ u32 sm[];
    const int e   = blockIdx.z;
    const int off = g_offs[e];
    const int n_e = g_offs[e + 1] - off;
    const int m0  = blockIdx.x * 128;
    if (m0 >= n_e) return;
    const int n0  = blockIdx.y * 128;

    const u32 smb = (u32)__cvta_generic_to_shared(sm);
    const int tid = threadIdx.x, wid = tid >> 5, lane = tid & 31;
    const int g = lane >> 2, tig = lane & 3;
    const int wm = wid >> 2, wn = wid & 3;

    const int lmat = lane >> 3, lrow = lane & 7;
    const int aoff = ((lmat & 1) * 8 + lrow) * AS + (lmat >> 1) * 4;

    const int arow = tid >> 2, aq = tid & 3;
    const int ar   = off + min(m0 + arow, n_e - 1);
    const char* aSrc = (const char*)(g_fuse + (size_t)ar * Ff) + aq * 32;
    const int kb = tid >> 4, oct = tid & 15;
    const char* bSrc = (const char*)(wd + (size_t)e * Ff * Dd + (size_t)kb * Dd + n0) + oct * 32;
    const u32 aDst = smb + arow * (AS * 4) + aq * 32;
    const u32 bDst = smb + A_TILE_U32 * 4 + kb * (BS * 4) + oct * 32;

    auto issue = [&](int it, int s) {
        const u32 so = s * (G2_STAGE_U32 * 4);
        const char* as = aSrc + (size_t)it * 128;
        const char* bs = bSrc + (size_t)it * (32 * Dd * 4);
        CPA(aDst + so,      as);      CPA(aDst + so + 16, as + 16);
        CPA(bDst + so,      bs);      CPA(bDst + so + 16, bs + 16);
    };

    float c[2][4][4];
#pragma unroll
    for (int i = 0; i < 2; i++)
#pragma unroll
        for (int j = 0; j < 4; j++)
#pragma unroll
            for (int r = 0; r < 4; r++) c[i][j][r] = 0.f;

    const int NIT = Ff / 32;   // 128
    issue(0, 0); CPCOMMIT();
    issue(1, 1); CPCOMMIT();
    issue(2, 2); CPCOMMIT();

#pragma unroll 1
    for (int it = 0; it < NIT; ++it) {
        const int s = it & 3;
        CPWAIT(2);
        __syncthreads();
        if (it + 3 < NIT) issue(it + 3, (it + 3) & 3);
        CPCOMMIT();

        const u32 Ab = smb + s * (G2_STAGE_U32 * 4) + (wm * 32 * AS + aoff) * 4;
        const u32* A = sm + s * G2_STAGE_U32;
        const u32* B = A + A_TILE_U32;

#pragma unroll
        for (int ks = 0; ks < 4; ++ks) {
            const int kk = ks * 8;
            u32 a[2][4];
            ldsm4(a[0], Ab + kk * 4);
            ldsm4(a[1], Ab + (16 * AS + kk) * 4);
#pragma unroll
            for (int nt = 0; nt < 4; nt++) {
                const int nb = wn * 32 + nt * 8 + g;
                u32 b0 = f2tf(__uint_as_float(B[(kk + tig) * BS + nb]));
                u32 b1 = f2tf(__uint_as_float(B[(kk + tig + 4) * BS + nb]));
#pragma unroll
                for (int mt = 0; mt < 2; mt++)
                    mma8(c[mt][nt], a[mt], b0, b1);
            }
        }
    }

    // epilogue: scatter rows by rid (each rid written exactly once)
#pragma unroll
    for (int mt = 0; mt < 2; mt++) {
        const int r0 = m0 + wm * 32 + mt * 16 + g;
        const int rlo = (r0 < n_e)     ? g_bucket[off + r0]     : -1;
        const int rhi = (r0 + 8 < n_e) ? g_bucket[off + r0 + 8] : -1;
#pragma unroll
        for (int nt = 0; nt < 4; nt++) {
            const int n = n0 + wn * 32 + nt * 8 + 2 * tig;
            if (rlo >= 0) {
                float2 v; v.x = c[mt][nt][0]; v.y = c[mt][nt][1];
                *(float2*)&g_down[(size_t)rlo * Dd + n] = v;
            }
            if (rhi >= 0) {
                float2 v; v.x = c[mt][nt][2]; v.y = c[mt][nt][3];
                *(float2*)&g_down[(size_t)rhi * Dd + n] = v;
            }
        }
    }
}

// ---------------------- 6. Weighted combine ----------------------
__global__ void combine_kernel(float* __restrict__ out) {
    int i = blockIdx.x * blockDim.x + threadIdx.x;
    const int n4 = Tt * Dd / 4;
    if (i >= n4) return;
    int t = i / (Dd / 4);
    int c = i % (Dd / 4);
    float w0 = g_topw[t * 2 + 0];
    float w1 = g_topw[t * 2 + 1];
    float4 a = ((const float4*)(g_down + (size_t)(t * 2 + 0) * Dd))[c];
    float4 b = ((const float4*)(g_down + (size_t)(t * 2 + 1) * Dd))[c];
    float4 r;
    r.x = w0 * a.x + w1 * b.x;
    r.y = w0 * a.y + w1 * b.y;
    r.z = w0 * a.z + w1 * b.z;
    r.w = w0 * a.w + w1 * b.w;
    ((float4*)out)[i] = r;
}

// ---------------------- launch ----------------------
extern "C" void kernel_launch(void* const* d_in, const int* in_sizes, int n_in,
                              void* d_out, int out_size) {
    const float* x  = (const float*)d_in[0];
    const float* rw = (const float*)d_in[1];
    const float* wg = (const float*)d_in[2];
    const float* wu = (const float*)d_in[3];
    const float* wd = (const float*)d_in[4];
    float* out = (float*)d_out;

    static int configured = 0;
    if (!configured) {
        cudaFuncSetAttribute(gemm1_mma, cudaFuncAttributeMaxDynamicSharedMemorySize, G1_SMEM_BYTES);
        cudaFuncSetAttribute(gemm2_mma, cudaFuncAttributeMaxDynamicSharedMemorySize, G2_SMEM_BYTES);
        configured = 1;
    }

    router_kernel<<<Tt / 8, 256>>>(x, rw);
    compact_kernel<<<1, 256>>>();
    convert_x_kernel<<<(Tt * Dd / 4 + 255) / 256, 256>>>(x);

    dim3 g1(NROWS / 128, Ff / 128, Ee);   // m fastest: weight-tile L2 reuse
    gemm1_mma<<<g1, 512, G1_SMEM_BYTES>>>(wg, wu);

    dim3 g2(NROWS / 128, Dd / 128, Ee);
    gemm2_mma<<<g2, 512, G2_SMEM_BYTES>>>(wd);

    combine_kernel<<<(Tt * Dd / 4 + 255) / 256, 256>>>(out);
}